// round 8
// baseline (speedup 1.0000x reference)
#include <cuda_runtime.h>

// Problem constants
#define T_STEPS 500
#define BATCH   1024
#define NDIM    256
#define ALPHA_F 0.995f   // 1 - 0.05/10
#define VTH_F   1.0f

// Chunking
#define CHUNK_T      20
#define N_CHUNKS     (T_STEPS / CHUNK_T)      // 25
#define ROWS_CHUNK   (CHUNK_T * BATCH)        // 20480 rows / chunk
#define TPB          256
#define C_BLOCKS     4                        // consumer blocks (first in grid)
#define ROWS_PB      8                        // 1 row per warp, 8 warps per block
#define BPC          (ROWS_CHUNK / ROWS_PB)   // 2560 producer blocks per chunk
#define P_BLOCKS     (N_CHUNKS * BPC)         // 64000 one-shot producer blocks

// Scratch: per-(t,b) input currents (2 MB, L2-resident) + sync flags
__device__ float    g_s[T_STEPS * BATCH];
__device__ unsigned g_flag[N_CHUNKS];   // #producer blocks done with chunk c
__device__ unsigned g_done[N_CHUNKS];   // #consumer blocks done (self-clean)

__device__ __forceinline__ unsigned ld_acquire_gpu(const unsigned* p) {
    unsigned v;
    asm volatile("ld.acquire.gpu.u32 %0, [%1];" : "=r"(v) : "l"(p) : "memory");
    return v;
}

__global__ void __launch_bounds__(TPB) lif_fused_kernel(
    const float* __restrict__ x,      // [T, B, N]
    const float* __restrict__ w,      // [N]
    float* __restrict__ out)          // [2, T, B]  (v then z)
{
    const int tid = threadIdx.x;

    if (blockIdx.x >= C_BLOCKS) {
        // ========== PRODUCER (one-shot: 8 rows of one chunk) ==========
        // Body identical to the R1 standalone GEMV that measured 7.1 TB/s:
        // 1 row/warp, 2 float4 loads/thread, ~32 regs -> high occupancy.
        const unsigned pb   = blockIdx.x - C_BLOCKS;   // 0..63999, chunk-major
        const unsigned c    = pb / BPC;                // chunk id
        const unsigned slab = pb % BPC;                // block-within-chunk
        const int warp = tid >> 5;
        const int lane = tid & 31;

        const long long row = (long long)c * ROWS_CHUNK + slab * ROWS_PB + warp;

        const float4* wv = reinterpret_cast<const float4*>(w);
        const float4 w0 = wv[lane];
        const float4 w1 = wv[lane + 32];

        const float4* xr = reinterpret_cast<const float4*>(x + row * NDIM);
        const float4 a0 = xr[lane];
        const float4 a1 = xr[lane + 32];

        float acc = a0.x * w0.x + a0.y * w0.y + a0.z * w0.z + a0.w * w0.w
                  + a1.x * w1.x + a1.y * w1.y + a1.z * w1.z + a1.w * w1.w;

        #pragma unroll
        for (int off = 16; off > 0; off >>= 1)
            acc += __shfl_xor_sync(0xffffffffu, acc, off);

        if (lane == 0) g_s[row] = acc;

        __syncthreads();                  // block's g_s stores complete
        if (tid == 0) {
            __threadfence();              // publish before counting
            atomicAdd(&g_flag[c], 1u);
        }
        // block exits; scheduler refills the SM slot with a fresh block
    } else {
        // ================= CONSUMER (persistent, 25 chunks) =================
        const int b = blockIdx.x * TPB + tid;   // 0..1023
        float* __restrict__ vout = out;                               // [T, B]
        float* __restrict__ zout = out + (long long)T_STEPS * BATCH;  // [T, B]

        float v = 0.0f, z = 0.0f;

        #pragma unroll 1
        for (int c = 0; c < N_CHUNKS; ++c) {
            if (tid == 0) {
                while (ld_acquire_gpu(&g_flag[c]) < BPC) { }
            }
            __syncthreads();   // order all threads after the acquire

            const int tbase = c * CHUNK_T;

            float s[CHUNK_T];
            #pragma unroll
            for (int i = 0; i < CHUNK_T; ++i)
                s[i] = g_s[(tbase + i) * BATCH + b];

            #pragma unroll
            for (int i = 0; i < CHUNK_T; ++i) {
                v = ALPHA_F * v + s[i] - z;
                z = (v > VTH_F) ? 1.0f : 0.0f;
                const int t = tbase + i;
                vout[(long long)t * BATCH + b] = v;
                zout[(long long)t * BATCH + b] = z;
            }

            __syncthreads();
            // self-clean flags for next graph replay: last consumer block resets
            if (tid == 0) {
                if (atomicAdd(&g_done[c], 1u) == C_BLOCKS - 1) {
                    g_flag[c] = 0;
                    g_done[c] = 0;
                }
            }
        }
    }
}

// ---------------------------------------------------------------------------
extern "C" void kernel_launch(void* const* d_in, const int* in_sizes, int n_in,
                              void* d_out, int out_size)
{
    const float* x = (const float*)d_in[0];   // [T, B, N] fp32
    const float* w = (const float*)d_in[1];   // [N] fp32
    float* out = (float*)d_out;               // [2, T, B] fp32

    lif_fused_kernel<<<C_BLOCKS + P_BLOCKS, TPB>>>(x, w, out);
}

// round 9
// speedup vs baseline: 1.2370x; 1.2370x over previous
#include <cuda_runtime.h>

// Problem constants
#define T_STEPS 500
#define BATCH   1024
#define NDIM    256
#define ALPHA_F 0.995f   // 1 - 0.05/10
#define VTH_F   1.0f

// Chunking
#define CHUNK_T      20
#define N_CHUNKS     (T_STEPS / CHUNK_T)      // 25
#define ROWS_CHUNK   (CHUNK_T * BATCH)        // 20480 rows / chunk
#define TPB          512                      // 16 warps
#define C_BLOCKS     2                        // consumer blocks (first in grid)
#define ROWS_PW      2                        // rows per warp (low reg pressure)
#define ROWS_PB      (ROWS_PW * (TPB / 32))   // 32 rows / block
#define BPC          (ROWS_CHUNK / ROWS_PB)   // 640 producer blocks per chunk
#define P_BLOCKS     (N_CHUNKS * BPC)         // 16000 one-shot producer blocks

// Scratch: per-(t,b) input currents (2 MB, L2-resident) + sync flags
__device__ float    g_s[T_STEPS * BATCH];
__device__ unsigned g_flag[N_CHUNKS];   // #producer blocks done with chunk c
__device__ unsigned g_done[N_CHUNKS];   // #consumer blocks done (self-clean)

__device__ __forceinline__ unsigned ld_acquire_gpu(const unsigned* p) {
    unsigned v;
    asm volatile("ld.acquire.gpu.u32 %0, [%1];" : "=r"(v) : "l"(p) : "memory");
    return v;
}

__global__ void __launch_bounds__(TPB) lif_fused_kernel(
    const float* __restrict__ x,      // [T, B, N]
    const float* __restrict__ w,      // [N]
    float* __restrict__ out)          // [2, T, B]  (v then z)
{
    const int tid = threadIdx.x;

    if (blockIdx.x >= C_BLOCKS) {
        // ========== PRODUCER (one-shot: 32 rows of one chunk) ==========
        // 2 rows/warp keeps only 4 float4 live per thread (~40 regs ->
        // ~75% occupancy) while the block-level fence is amortized over
        // 32 rows (R7's proven granularity). 16 warps/block.
        const unsigned pb   = blockIdx.x - C_BLOCKS;   // chunk-major
        const unsigned c    = pb / BPC;                // chunk id
        const unsigned slab = pb % BPC;                // block-within-chunk
        const int warp = tid >> 5;
        const int lane = tid & 31;

        const long long rbase = (long long)c * ROWS_CHUNK
                              + slab * ROWS_PB + warp * ROWS_PW;

        const float4* wv = reinterpret_cast<const float4*>(w);
        const float4 w0 = wv[lane];
        const float4 w1 = wv[lane + 32];

        // 4 independent float4 loads (2 rows x 2 halves)
        const float4* xr0 = reinterpret_cast<const float4*>(x + rbase * NDIM);
        const float4* xr1 = reinterpret_cast<const float4*>(x + (rbase + 1) * NDIM);
        const float4 a00 = xr0[lane];
        const float4 a01 = xr0[lane + 32];
        const float4 a10 = xr1[lane];
        const float4 a11 = xr1[lane + 32];

        float acc0 = a00.x * w0.x + a00.y * w0.y + a00.z * w0.z + a00.w * w0.w
                   + a01.x * w1.x + a01.y * w1.y + a01.z * w1.z + a01.w * w1.w;
        float acc1 = a10.x * w0.x + a10.y * w0.y + a10.z * w0.z + a10.w * w0.w
                   + a11.x * w1.x + a11.y * w1.y + a11.z * w1.z + a11.w * w1.w;

        #pragma unroll
        for (int off = 16; off > 0; off >>= 1) {
            acc0 += __shfl_xor_sync(0xffffffffu, acc0, off);
            acc1 += __shfl_xor_sync(0xffffffffu, acc1, off);
        }

        if (lane == 0) {
            g_s[rbase]     = acc0;
            g_s[rbase + 1] = acc1;
        }

        __syncthreads();                  // block's g_s stores complete
        if (tid == 0) {
            __threadfence();              // publish before counting
            atomicAdd(&g_flag[c], 1u);
        }
        // block exits; scheduler refills the SM slot with a fresh block
    } else {
        // ================= CONSUMER (persistent, 25 chunks) =================
        const int b = blockIdx.x * TPB + tid;   // 0..1023
        float* __restrict__ vout = out;                               // [T, B]
        float* __restrict__ zout = out + (long long)T_STEPS * BATCH;  // [T, B]

        float v = 0.0f, z = 0.0f;

        #pragma unroll 1
        for (int c = 0; c < N_CHUNKS; ++c) {
            if (tid == 0) {
                while (ld_acquire_gpu(&g_flag[c]) < BPC) { }
            }
            __syncthreads();   // order all threads after the acquire

            const int tbase = c * CHUNK_T;

            float s[CHUNK_T];
            #pragma unroll
            for (int i = 0; i < CHUNK_T; ++i)
                s[i] = g_s[(tbase + i) * BATCH + b];

            #pragma unroll
            for (int i = 0; i < CHUNK_T; ++i) {
                v = ALPHA_F * v + s[i] - z;
                z = (v > VTH_F) ? 1.0f : 0.0f;
                const int t = tbase + i;
                vout[(long long)t * BATCH + b] = v;
                zout[(long long)t * BATCH + b] = z;
            }

            __syncthreads();
            // self-clean flags for next graph replay: last consumer block resets
            if (tid == 0) {
                if (atomicAdd(&g_done[c], 1u) == C_BLOCKS - 1) {
                    g_flag[c] = 0;
                    g_done[c] = 0;
                }
            }
        }
    }
}

// ---------------------------------------------------------------------------
extern "C" void kernel_launch(void* const* d_in, const int* in_sizes, int n_in,
                              void* d_out, int out_size)
{
    const float* x = (const float*)d_in[0];   // [T, B, N] fp32
    const float* w = (const float*)d_in[1];   // [N] fp32
    float* out = (float*)d_out;               // [2, T, B] fp32

    lif_fused_kernel<<<C_BLOCKS + P_BLOCKS, TPB>>>(x, w, out);
}